// round 1
// baseline (speedup 1.0000x reference)
#include <cuda_runtime.h>

#define HH 512
#define WW 512
#define BATCH 16
#define RPB 4        // rows per block
#define PXT 8        // pixels per thread along x
#define TX 64        // threads in x (TX*PXT = 512)
#define TILE_W 516   // 512 + 2 halo each side
#define TILE_STRIDE 520
#define TILE_H (RPB + 4)

__device__ __forceinline__ void ce(float& a, float& b) {
    float t = fminf(a, b);
    b = fmaxf(a, b);
    a = t;
}

// optimal 9-CE sorting network for 5 elements
__device__ __forceinline__ void sort5(float v[5]) {
    ce(v[0], v[1]); ce(v[3], v[4]); ce(v[2], v[4]);
    ce(v[2], v[3]); ce(v[0], v[3]); ce(v[0], v[2]);
    ce(v[1], v[4]); ce(v[1], v[3]); ce(v[1], v[2]);
}

// Batcher odd-even merge of two sorted 5-lists -> sorted 10-list (13 CE)
__device__ __forceinline__ void merge55(const float x[5], const float y[5], float z[10]) {
    // P = oem33 on even-index elements (x0,x2,x4)/(y0,y2,y4)
    float t0 = fminf(x[0], y[0]), t1 = fmaxf(x[0], y[0]);
    float w0 = fminf(x[4], y[4]), w1 = fmaxf(x[4], y[4]);
    float r1 = fminf(w0, t1),     r2 = fmaxf(w0, t1);
    float s0 = fminf(x[2], y[2]), s1 = fmaxf(x[2], y[2]);
    float p0 = t0;
    float p1 = fminf(s0, r1), p2 = fmaxf(s0, r1);
    float p3 = fminf(s1, r2), p4 = fmaxf(s1, r2);
    float p5 = w1;
    // Q = oem22 on odd-index elements (x1,x3)/(y1,y3)
    float a0 = fminf(x[1], y[1]), a1 = fmaxf(x[1], y[1]);
    float b0 = fminf(x[3], y[3]), b1 = fmaxf(x[3], y[3]);
    float q0 = a0;
    float q1 = fminf(b0, a1), q2 = fmaxf(b0, a1);
    float q3 = b1;
    // combine
    z[0] = p0;
    z[1] = fminf(q0, p1); z[2] = fmaxf(q0, p1);
    z[3] = fminf(q1, p2); z[4] = fmaxf(q1, p2);
    z[5] = fminf(q2, p3); z[6] = fmaxf(q2, p3);
    z[7] = fminf(q3, p4); z[8] = fmaxf(q3, p4);
    z[9] = p5;
}

// Exact median of 25 given 5 sorted columns.
// m1=merge(A,B), m2=merge(C,D); pruned OEM(10,10) -> S[7..12] only; then
// rank-13 of S(20) U E(5) via min_j max(S[12-j], E[j-1]).
__device__ __forceinline__ float median25(const float A[5], const float B[5],
                                          const float C[5], const float D[5],
                                          const float E[5]) {
    float m1[10], m2[10];
    merge55(A, B, m1);
    merge55(C, D, m2);

    // D-part: merge of even-index elements of m1/m2, outputs d4,d5,d6 only
    float t1  = fmaxf(m1[0], m2[0]);
    float w0  = fminf(m1[8], m2[8]);
    float r1  = fminf(w0, t1),  r2 = fmaxf(w0, t1);
    float s0  = fminf(m1[4], m2[4]), s1 = fmaxf(m1[4], m2[4]);
    float p2  = fmaxf(s0, r1),  p3 = fminf(s1, r2);
    float t1q = fmaxf(m1[2], m2[2]);
    float w0q = fminf(m1[6], m2[6]);
    float q1  = fminf(w0q, t1q), q2 = fmaxf(w0q, t1q);
    float d4  = fmaxf(q1, p2);
    float d5  = fminf(q2, p3), d6 = fmaxf(q2, p3);

    // G-part: merge of odd-index elements, outputs g3,g4,g5 only
    float t1g = fmaxf(m1[1], m2[1]);
    float w0g = fminf(m1[9], m2[9]);
    float r1g = fminf(w0g, t1g), r2g = fmaxf(w0g, t1g);
    float s0g = fminf(m1[5], m2[5]), s1g = fmaxf(m1[5], m2[5]);
    float p2g = fmaxf(s0g, r1g), p3g = fminf(s1g, r2g);
    float t1h = fmaxf(m1[3], m2[3]);
    float w0h = fminf(m1[7], m2[7]);
    float q1g = fminf(w0h, t1h), q2g = fmaxf(w0h, t1h);
    float g3  = fminf(q1g, p2g), g4 = fmaxf(q1g, p2g);
    float g5  = fminf(q2g, p3g);

    // S[7..12] of the 20-element merge
    float s7  = fminf(g3, d4), s8  = fmaxf(g3, d4);
    float s9  = fminf(g4, d5), s10 = fmaxf(g4, d5);
    float s11 = fminf(g5, d6), s12 = fmaxf(g5, d6);

    // 13th smallest of S(20) U E(5)
    float med = s12;
    med = fminf(med, fmaxf(s11, E[0]));
    med = fminf(med, fmaxf(s10, E[1]));
    med = fminf(med, fmaxf(s9,  E[2]));
    med = fminf(med, fmaxf(s8,  E[3]));
    med = fminf(med, fmaxf(s7,  E[4]));
    return med;
}

__global__ __launch_bounds__(TX * RPB)
void Net_29291676958726_kernel(const float* __restrict__ x,
                               const float* __restrict__ noise_var,
                               const float* __restrict__ noise_bias,
                               float* __restrict__ out) {
    __shared__ float tile[TILE_H][TILE_STRIDE];

    const int b   = blockIdx.y;
    const int rb  = blockIdx.x * RPB;
    const int tid = threadIdx.y * TX + threadIdx.x;
    const float* __restrict__ xb_ptr = x + (size_t)b * HH * WW;

    // cooperative zero-padded tile load (rows rb-2 .. rb+RPB+1, cols -2..513)
    for (int idx = tid; idx < TILE_H * TILE_W; idx += TX * RPB) {
        int r  = idx / TILE_W;
        int c  = idx % TILE_W;
        int gr = rb - 2 + r;
        int gc = c - 2;
        float v = 0.0f;
        if ((unsigned)gr < HH && (unsigned)gc < WW)
            v = xb_ptr[gr * WW + gc];
        tile[r][c] = v;
    }
    __syncthreads();

    const float nv = noise_var[0];
    const float nb = noise_bias[0];

    const int ty    = threadIdx.y;          // tile-relative pixel row = ty (+2 offset)
    const int xbase = threadIdx.x * PXT;    // tile col of leftmost window column

    float cs[5][5];      // sorted columns (rotating slots)
    float csum[5], csq[5];

    // prime first 4 columns of the first window
#pragma unroll
    for (int j = 0; j < 4; j++) {
        float v[5];
#pragma unroll
        for (int k = 0; k < 5; k++) v[k] = tile[ty + k][xbase + j];
        float s  = ((v[0] + v[1]) + (v[2] + v[3])) + v[4];
        float sq = 0.0f;
#pragma unroll
        for (int k = 0; k < 5; k++) sq = fmaf(v[k], v[k], sq);
        sort5(v);
#pragma unroll
        for (int k = 0; k < 5; k++) cs[j][k] = v[k];
        csum[j] = s;
        csq[j]  = sq;
    }

    float* __restrict__ orow = out + (size_t)b * HH * WW + (size_t)(rb + ty) * WW + xbase;

#pragma unroll
    for (int i = 0; i < PXT; i++) {
        const int slot = (4 + i) % 5;   // compile-time after unroll
        float v[5];
#pragma unroll
        for (int k = 0; k < 5; k++) v[k] = tile[ty + k][xbase + 4 + i];
        float s  = ((v[0] + v[1]) + (v[2] + v[3])) + v[4];
        float sq = 0.0f;
#pragma unroll
        for (int k = 0; k < 5; k++) sq = fmaf(v[k], v[k], sq);
        sort5(v);
#pragma unroll
        for (int k = 0; k < 5; k++) cs[slot][k] = v[k];
        csum[slot] = s;
        csq[slot]  = sq;

        float sumall = ((csum[0] + csum[1]) + (csum[2] + csum[3])) + csum[4];
        float sqall  = ((csq[0] + csq[1]) + (csq[2] + csq[3])) + csq[4];
        // unbiased variance: (sum(x^2) - (sum x)^2/25) / 24
        float svar = (sqall - sumall * sumall * 0.04f) * (1.0f / 24.0f);
        svar = fmaxf(svar, 0.0f);

        float xc  = tile[ty + 2][xbase + 2 + i];
        float med = median25(cs[0], cs[1], cs[2], cs[3], cs[4]);

        float y = xc - nv * __fdividef(xc - med + nb, svar + 1e-10f);
        orow[i] = fmaxf(y, 0.0f);
    }
}

extern "C" void kernel_launch(void* const* d_in, const int* in_sizes, int n_in,
                              void* d_out, int out_size) {
    const float* x  = (const float*)d_in[0];
    const float* nv = (const float*)d_in[1];
    const float* nb = (const float*)d_in[2];
    float* out = (float*)d_out;

    dim3 block(TX, RPB);
    dim3 grid(HH / RPB, BATCH);
    Net_29291676958726_kernel<<<grid, block>>>(x, nv, nb, out);
}

// round 2
// speedup vs baseline: 1.1074x; 1.1074x over previous
#include <cuda_runtime.h>

#define HH 512
#define WW 512
#define BATCH 16
#define RPB 4        // rows per block
#define PXT 8        // pixels per thread along x
#define TX 64        // threads in x (TX*PXT = 512)
#define TILE_W 516   // 512 + 2 halo each side
#define TILE_STRIDE 520
#define TILE_H (RPB + 4)

__device__ __forceinline__ void ce(float& a, float& b) {
    float t = fminf(a, b);
    b = fmaxf(a, b);
    a = t;
}

// optimal 9-CE sorting network for 5 elements
__device__ __forceinline__ void sort5(float v[5]) {
    ce(v[0], v[1]); ce(v[3], v[4]); ce(v[2], v[4]);
    ce(v[2], v[3]); ce(v[0], v[3]); ce(v[0], v[2]);
    ce(v[1], v[4]); ce(v[1], v[3]); ce(v[1], v[2]);
}

// Batcher odd-even merge of two sorted 5-lists -> sorted 10-list (13 CE)
__device__ __forceinline__ void merge55(const float x[5], const float y[5], float z[10]) {
    // P = oem33 on even-index elements (x0,x2,x4)/(y0,y2,y4)
    float t0 = fminf(x[0], y[0]), t1 = fmaxf(x[0], y[0]);
    float w0 = fminf(x[4], y[4]), w1 = fmaxf(x[4], y[4]);
    float r1 = fminf(w0, t1),     r2 = fmaxf(w0, t1);
    float s0 = fminf(x[2], y[2]), s1 = fmaxf(x[2], y[2]);
    float p0 = t0;
    float p1 = fminf(s0, r1), p2 = fmaxf(s0, r1);
    float p3 = fminf(s1, r2), p4 = fmaxf(s1, r2);
    float p5 = w1;
    // Q = oem22 on odd-index elements (x1,x3)/(y1,y3)
    float a0 = fminf(x[1], y[1]), a1 = fmaxf(x[1], y[1]);
    float b0 = fminf(x[3], y[3]), b1 = fmaxf(x[3], y[3]);
    float q0 = a0;
    float q1 = fminf(b0, a1), q2 = fmaxf(b0, a1);
    float q3 = b1;
    // combine
    z[0] = p0;
    z[1] = fminf(q0, p1); z[2] = fmaxf(q0, p1);
    z[3] = fminf(q1, p2); z[4] = fmaxf(q1, p2);
    z[5] = fminf(q2, p3); z[6] = fmaxf(q2, p3);
    z[7] = fminf(q3, p4); z[8] = fmaxf(q3, p4);
    z[9] = p5;
}

// Pruned OEM(10,10) of two sorted 10-lists: produce only ranks 7..12
// (s[0]=s7 ... s[5]=s12) of the merged 20-list.
__device__ __forceinline__ void prune_mid(const float m1[10], const float m2[10], float s[6]) {
    // D-part: merge of even-index elements of m1/m2, outputs d4,d5,d6 only
    float t1  = fmaxf(m1[0], m2[0]);
    float w0  = fminf(m1[8], m2[8]);
    float r1  = fminf(w0, t1),  r2 = fmaxf(w0, t1);
    float s0  = fminf(m1[4], m2[4]), s1 = fmaxf(m1[4], m2[4]);
    float p2  = fmaxf(s0, r1),  p3 = fminf(s1, r2);
    float t1q = fmaxf(m1[2], m2[2]);
    float w0q = fminf(m1[6], m2[6]);
    float q1  = fminf(w0q, t1q), q2 = fmaxf(w0q, t1q);
    float d4  = fmaxf(q1, p2);
    float d5  = fminf(q2, p3), d6 = fmaxf(q2, p3);

    // G-part: merge of odd-index elements, outputs g3,g4,g5 only
    float t1g = fmaxf(m1[1], m2[1]);
    float w0g = fminf(m1[9], m2[9]);
    float r1g = fminf(w0g, t1g), r2g = fmaxf(w0g, t1g);
    float s0g = fminf(m1[5], m2[5]), s1g = fmaxf(m1[5], m2[5]);
    float p2g = fmaxf(s0g, r1g), p3g = fminf(s1g, r2g);
    float t1h = fmaxf(m1[3], m2[3]);
    float w0h = fminf(m1[7], m2[7]);
    float q1g = fminf(w0h, t1h), q2g = fmaxf(w0h, t1h);
    float g3  = fminf(q1g, p2g), g4 = fmaxf(q1g, p2g);
    float g5  = fminf(q2g, p3g);

    s[0] = fminf(g3, d4); s[1] = fmaxf(g3, d4);
    s[2] = fminf(g4, d5); s[3] = fmaxf(g4, d5);
    s[4] = fminf(g5, d6); s[5] = fmaxf(g5, d6);
}

// 13th smallest of S(20) U E(5): E sorted ascending, s[0..5]=s7..s12.
__device__ __forceinline__ float sel13(const float s[6], const float E[5]) {
    float med = s[5];
    med = fminf(med, fmaxf(s[4], E[0]));
    med = fminf(med, fmaxf(s[3], E[1]));
    med = fminf(med, fmaxf(s[2], E[2]));
    med = fminf(med, fmaxf(s[1], E[3]));
    med = fminf(med, fmaxf(s[0], E[4]));
    return med;
}

__global__ __launch_bounds__(TX * RPB)
void Net_29291676958726_kernel(const float* __restrict__ x,
                               const float* __restrict__ noise_var,
                               const float* __restrict__ noise_bias,
                               float* __restrict__ out) {
    __shared__ float tile[TILE_H][TILE_STRIDE];

    const int b   = blockIdx.y;
    const int rb  = blockIdx.x * RPB;
    const int tid = threadIdx.y * TX + threadIdx.x;
    const float* __restrict__ xb_ptr = x + (size_t)b * HH * WW;

    // cooperative zero-padded tile load (rows rb-2 .. rb+RPB+1, cols -2..513)
    for (int idx = tid; idx < TILE_H * TILE_W; idx += TX * RPB) {
        int r  = idx / TILE_W;
        int c  = idx % TILE_W;
        int gr = rb - 2 + r;
        int gc = c - 2;
        float v = 0.0f;
        if ((unsigned)gr < HH && (unsigned)gc < WW)
            v = xb_ptr[gr * WW + gc];
        tile[r][c] = v;
    }
    __syncthreads();

    const float nv = noise_var[0];
    const float nb = noise_bias[0];

    const int ty    = threadIdx.y;
    const int xbase = threadIdx.x * PXT;

    // Per-thread column state. Column j corresponds to tile col xbase+j,
    // j = 0..11 (8 pixels + 4 halo). Full unroll -> compiler handles liveness.
    float sc[12][5];     // sorted columns
    float cen[12];       // tile[ty+2][xbase+j] (window centers)
    float csum[12], csq[12];

    // prime columns 0..3
#pragma unroll
    for (int j = 0; j < 4; j++) {
        float v[5];
#pragma unroll
        for (int k = 0; k < 5; k++) v[k] = tile[ty + k][xbase + j];
        csum[j] = ((v[0] + v[1]) + (v[2] + v[3])) + v[4];
        csq[j]  = fmaf(v[0], v[0], fmaf(v[1], v[1], fmaf(v[2], v[2], fmaf(v[3], v[3], v[4] * v[4]))));
        cen[j]  = v[2];
        sort5(v);
#pragma unroll
        for (int k = 0; k < 5; k++) sc[j][k] = v[k];
    }

    float M[10];                       // M_0 = merge(c1, c2)
    merge55(sc[1], sc[2], M);

    // invariant entering pair t: ws/wq = sum over columns [2t .. 2t+3]
    float ws = ((csum[0] + csum[1]) + (csum[2] + csum[3]));
    float wq = ((csq[0]  + csq[1])  + (csq[2]  + csq[3]));

    float2* __restrict__ orow =
        (float2*)(out + (size_t)b * HH * WW + (size_t)(rb + ty) * WW + xbase);

#pragma unroll
    for (int t = 0; t < PXT / 2; t++) {
        // new columns 2t+4 and 2t+5
#pragma unroll
        for (int jj = 0; jj < 2; jj++) {
            const int j = 2 * t + 4 + jj;
            float v[5];
#pragma unroll
            for (int k = 0; k < 5; k++) v[k] = tile[ty + k][xbase + j];
            csum[j] = ((v[0] + v[1]) + (v[2] + v[3])) + v[4];
            csq[j]  = fmaf(v[0], v[0], fmaf(v[1], v[1], fmaf(v[2], v[2], fmaf(v[3], v[3], v[4] * v[4]))));
            cen[j]  = v[2];
            sort5(v);
#pragma unroll
            for (int k = 0; k < 5; k++) sc[j][k] = v[k];
        }

        float N[10];                   // N_t = merge(c_{2t+3}, c_{2t+4}) = M_{t+1}
        merge55(sc[2 * t + 3], sc[2 * t + 4], N);

        float s[6];
        prune_mid(M, N, s);            // shared middle ranks for the pair

        // even pixel p = 2t: window cols [2t .. 2t+4], E = sc[2t]
        float ws_e = ws + csum[2 * t + 4];
        float wq_e = wq + csq[2 * t + 4];
        float var_e = fmaxf((wq_e - ws_e * ws_e * 0.04f) * (1.0f / 24.0f), 0.0f);
        float med_e = sel13(s, sc[2 * t]);
        float xc_e  = cen[2 * t + 2];
        float y_e   = xc_e - nv * __fdividef(xc_e - med_e + nb, var_e + 1e-10f);

        // odd pixel p = 2t+1: window cols [2t+1 .. 2t+5], E = sc[2t+5]
        float ws_o = ws_e + csum[2 * t + 5] - csum[2 * t];
        float wq_o = wq_e + csq[2 * t + 5] - csq[2 * t];
        float var_o = fmaxf((wq_o - ws_o * ws_o * 0.04f) * (1.0f / 24.0f), 0.0f);
        float med_o = sel13(s, sc[2 * t + 5]);
        float xc_o  = cen[2 * t + 3];
        float y_o   = xc_o - nv * __fdividef(xc_o - med_o + nb, var_o + 1e-10f);

        orow[t] = make_float2(fmaxf(y_e, 0.0f), fmaxf(y_o, 0.0f));

        // carry to next pair: ws covers cols [2t+2 .. 2t+5]
        ws = ws_o - csum[2 * t + 1];
        wq = wq_o - csq[2 * t + 1];
#pragma unroll
        for (int k = 0; k < 10; k++) M[k] = N[k];
    }
}

extern "C" void kernel_launch(void* const* d_in, const int* in_sizes, int n_in,
                              void* d_out, int out_size) {
    const float* x  = (const float*)d_in[0];
    const float* nv = (const float*)d_in[1];
    const float* nb = (const float*)d_in[2];
    float* out = (float*)d_out;

    dim3 block(TX, RPB);
    dim3 grid(HH / RPB, BATCH);
    Net_29291676958726_kernel<<<grid, block>>>(x, nv, nb, out);
}